// round 1
// baseline (speedup 1.0000x reference)
#include <cuda_runtime.h>

#define T_STEPS 4096
#define RES     2048
#define NF      8
#define NO      8
#define GRID_B  128
#define BLOCK_B 256
#define NC      16     // output columns per CTA
#define CHUNK   256    // i-range per warp
#define PAIRS   64     // f32x2 pairs per lane (CHUNK/2 pairs split over 2 parities)

// Scratch (allocation-free rule: device globals)
__device__ float g_drive[T_STEPS * RES];   // 32 MB
__device__ float g_X[T_STEPS * RES];       // 32 MB
__device__ unsigned int g_counter;

__device__ __forceinline__ unsigned long long ffma2(unsigned long long a,
                                                    unsigned long long b,
                                                    unsigned long long c) {
    unsigned long long d;
    asm("fma.rn.f32x2 %0, %1, %2, %3;" : "=l"(d) : "l"(a), "l"(b), "l"(c));
    return d;
}

// ---------------------------------------------------------------------------
// Kernel A: drive[t][r] = win_bias[r] + inp[t] @ win_u[:, r]   (+ counter reset)
// ---------------------------------------------------------------------------
__global__ void drive_kernel(const float* __restrict__ inp,
                             const float* __restrict__ Win) {
    int t = blockIdx.y;
    int r = blockIdx.x * blockDim.x + threadIdx.x;
    if (blockIdx.x == 0 && blockIdx.y == 0 && threadIdx.x == 0) g_counter = 0u;
    float acc = Win[r];                       // bias row (Win[0])
#pragma unroll
    for (int f = 0; f < NF; f++)
        acc += inp[t * NF + f] * Win[(1 + f) * RES + r];
    g_drive[t * RES + r] = acc;
}

// ---------------------------------------------------------------------------
// Kernel B: persistent scan. 128 CTAs, each owns 16 columns of W in REGISTERS.
//   lane l: col = l&15, parity p = l>>4. warp w: i-range [w*256, w*256+256).
//   lane handles i = w*256 + 4k + 2p (+1), k = 0..63 -> 64 f32x2 MACs/step.
//   x broadcast from SMEM (two distinct float2 addrs/warp -> conflict-free).
// ---------------------------------------------------------------------------
__global__ void __launch_bounds__(BLOCK_B, 1)
scan_kernel(const float* __restrict__ W) {
    __shared__ float sx[RES];          // current x (8 KB)
    __shared__ float sred[8 * NC];     // per-warp partials

    const int tid  = threadIdx.x;
    const int w    = tid >> 5;
    const int lane = tid & 31;
    const int col  = lane & 15;
    const int par  = lane >> 4;
    const int cbj  = blockIdx.x * NC;      // column base of this CTA
    const int jg   = cbj + col;            // global output column of this lane
    const int i0   = w * CHUNK;

    // --- Load this lane's W slice into registers (one-time, ~16 MB chip-wide)
    unsigned long long wr[PAIRS];
#pragma unroll
    for (int k = 0; k < PAIRS; k++) {
        int i = i0 + 4 * k + 2 * par;
        float2 f2;
        f2.x = __ldg(&W[(size_t)i * RES + jg]);
        f2.y = __ldg(&W[(size_t)(i + 1) * RES + jg]);
        wr[k] = *reinterpret_cast<unsigned long long*>(&f2);
    }

    // x_0 = 0
    for (int idx = tid; idx < RES; idx += BLOCK_B) sx[idx] = 0.0f;
    __syncthreads();

    const float2* sx2 = reinterpret_cast<const float2*>(sx);
    const int pbase = i0 / 2 + par;

    const float dmp = 0.3f;
    const float omd = 1.0f - 0.3f;

    for (int t = 0; t < T_STEPS; t++) {
        // Prefetch drive + old-x for the 16 finalizer threads (hides L2 latency)
        float drv = 0.0f, xold = 0.0f;
        if (tid < NC) {
            drv  = g_drive[t * RES + cbj + tid];
            xold = sx[cbj + tid];
        }

        // --- matvec partial: 64 x (broadcast LDS.64 + fma.f32x2)
        unsigned long long acc = 0ull;
#pragma unroll
        for (int k = 0; k < PAIRS; k++) {
            float2 xp = sx2[pbase + 2 * k];
            unsigned long long xv = *reinterpret_cast<unsigned long long*>(&xp);
            acc = ffma2(wr[k], xv, acc);
        }
        float2 a2 = *reinterpret_cast<float2*>(&acc);
        float s = a2.x + a2.y;
        s += __shfl_down_sync(0xffffffffu, s, 16);   // fold parity halves
        if (par == 0) sred[w * NC + col] = s;
        __syncthreads();

        // --- finalize 16 columns, write x_{t+1} to global
        if (tid < NC) {
            float tot = 0.0f;
#pragma unroll
            for (int ww = 0; ww < 8; ww++) tot += sred[ww * NC + tid];
            float xn = omd * xold + dmp * tanhf(drv + tot);
            g_X[t * RES + cbj + tid] = xn;
        }
        __syncthreads();   // order the 16 STGs before thread 0's release (cumulativity)

        if (t == T_STEPS - 1) break;

        // --- grid barrier: release-add, acquire-poll
        if (tid == 0) {
            asm volatile("red.release.gpu.add.u32 [%0], %1;"
                         :: "l"(&g_counter), "r"(1u) : "memory");
            unsigned target = (unsigned)GRID_B * (unsigned)(t + 1);
            unsigned v;
            do {
                asm volatile("ld.acquire.gpu.u32 %0, [%1];"
                             : "=r"(v) : "l"(&g_counter) : "memory");
            } while (v < target);
        }
        __syncthreads();

        // --- reload full x_{t+1} into SMEM (2 x LDG.128 per thread)
        const float4* xr = reinterpret_cast<const float4*>(&g_X[(size_t)t * RES]);
        float4* sx4 = reinterpret_cast<float4*>(sx);
        float4 v0 = xr[tid];
        float4 v1 = xr[tid + BLOCK_B];
        sx4[tid] = v0;
        sx4[tid + BLOCK_B] = v1;
        __syncthreads();
    }
}

// ---------------------------------------------------------------------------
// Kernel C: Y[t] = wout_bias + inp[t] @ wout_u + x_{t+1} @ wout_x
//   one warp per timestep; 8 timesteps per block.
// ---------------------------------------------------------------------------
__global__ void readout_kernel(const float* __restrict__ inp,
                               const float* __restrict__ Wout,
                               float* __restrict__ out) {
    const int w    = threadIdx.x >> 5;
    const int lane = threadIdx.x & 31;
    const int t    = blockIdx.x * 8 + w;

    float acc[NO];
#pragma unroll
    for (int o = 0; o < NO; o++) acc[o] = 0.0f;

    const float* xrow = &g_X[(size_t)t * RES];
    for (int it = 0; it < RES / 32; it++) {
        int r = it * 32 + lane;
        float xv = xrow[r];
        const float4* wrow =
            reinterpret_cast<const float4*>(&Wout[(size_t)(1 + NF + r) * NO]);
        float4 wa = wrow[0], wb = wrow[1];
        acc[0] += xv * wa.x; acc[1] += xv * wa.y;
        acc[2] += xv * wa.z; acc[3] += xv * wa.w;
        acc[4] += xv * wb.x; acc[5] += xv * wb.y;
        acc[6] += xv * wb.z; acc[7] += xv * wb.w;
    }
#pragma unroll
    for (int o = 0; o < NO; o++) {
#pragma unroll
        for (int sft = 16; sft > 0; sft >>= 1)
            acc[o] += __shfl_down_sync(0xffffffffu, acc[o], sft);
    }
    if (lane == 0) {
#pragma unroll
        for (int o = 0; o < NO; o++) {
            float y = Wout[o];
#pragma unroll
            for (int f = 0; f < NF; f++)
                y += inp[t * NF + f] * Wout[(1 + f) * NO + o];
            out[t * NO + o] = y + acc[o];
        }
    }
}

// ---------------------------------------------------------------------------
extern "C" void kernel_launch(void* const* d_in, const int* in_sizes, int n_in,
                              void* d_out, int out_size) {
    const float* inp  = (const float*)d_in[0];   // (4096, 8)
    const float* Win  = (const float*)d_in[1];   // (9, 2048)
    const float* W    = (const float*)d_in[2];   // (2048, 2048)
    const float* Wout = (const float*)d_in[3];   // (2057, 8)
    float* out = (float*)d_out;                  // (4096, 8) fp32

    dim3 ga(RES / 256, T_STEPS);
    drive_kernel<<<ga, 256>>>(inp, Win);
    scan_kernel<<<GRID_B, BLOCK_B>>>(W);
    readout_kernel<<<T_STEPS / 8, 256>>>(inp, Wout, out);
}